// round 8
// baseline (speedup 1.0000x reference)
#include <cuda_runtime.h>
#include <cuda_bf16.h>
#include <cstdint>

#define BATCH 8
#define SEQ   2048
#define DIM   128
#define EXP2_SCALE (0.08838834764831843f * 1.44269504088896340f)

typedef unsigned long long ull;

// ---------------- device scratch ----------------
__device__ float g_inv_rs[BATCH * SEQ];
__device__ __align__(16) __nv_bfloat16 g_qhi[BATCH * SEQ * DIM];
__device__ __align__(16) __nv_bfloat16 g_qlo[BATCH * SEQ * DIM];
__device__ __align__(16) __nv_bfloat16 g_vhi[BATCH * SEQ * DIM];  // reused as w_hi after pass1
__device__ __align__(16) __nv_bfloat16 g_vlo[BATCH * SEQ * DIM];  // reused as w_lo after pass1
// unnormalized exp(scores) in bf16 hi/lo (written by pass1, read by pass2)
__device__ __align__(16) __nv_bfloat16 g_uhi[(size_t)BATCH * SEQ * SEQ];
__device__ __align__(16) __nv_bfloat16 g_ulo[(size_t)BATCH * SEQ * SEQ];

// ---------------- cp.async ----------------
__device__ __forceinline__ void cp_async16(uint32_t smem_dst, const void* gsrc) {
    asm volatile("cp.async.ca.shared.global [%0], [%1], 16;\n"
                 :: "r"(smem_dst), "l"(gsrc));
}
#define CP_COMMIT() asm volatile("cp.async.commit_group;\n" ::: "memory")
#define CP_WAIT0()  asm volatile("cp.async.wait_group 0;\n" ::: "memory")
#define CP_WAIT1()  asm volatile("cp.async.wait_group 1;\n" ::: "memory")

__device__ __forceinline__ uint32_t smem_u32(const void* p) {
    uint32_t a;
    asm("{ .reg .u64 t; cvta.to.shared.u64 t, %1; cvt.u32.u64 %0, t; }"
        : "=r"(a) : "l"(p));
    return a;
}

// ---------------- mma / ldmatrix ----------------
__device__ __forceinline__ void ldm4(unsigned* r, uint32_t addr) {
    asm volatile("ldmatrix.sync.aligned.m8n8.x4.shared.b16 {%0,%1,%2,%3}, [%4];"
                 : "=r"(r[0]), "=r"(r[1]), "=r"(r[2]), "=r"(r[3]) : "r"(addr));
}
__device__ __forceinline__ void ldm4t(unsigned* r, uint32_t addr) {
    asm volatile("ldmatrix.sync.aligned.m8n8.x4.trans.shared.b16 {%0,%1,%2,%3}, [%4];"
                 : "=r"(r[0]), "=r"(r[1]), "=r"(r[2]), "=r"(r[3]) : "r"(addr));
}
__device__ __forceinline__ void mma16816(float* d, const unsigned* a,
                                         const unsigned* b) {
    asm volatile(
        "mma.sync.aligned.m16n8k16.row.col.f32.bf16.bf16.f32 "
        "{%0,%1,%2,%3}, {%4,%5,%6,%7}, {%8,%9}, {%0,%1,%2,%3};"
        : "+f"(d[0]), "+f"(d[1]), "+f"(d[2]), "+f"(d[3])
        : "r"(a[0]), "r"(a[1]), "r"(a[2]), "r"(a[3]), "r"(b[0]), "r"(b[1]));
}

// =====================================================================
// split kernel: q,v -> bf16 hi/lo
// =====================================================================
__global__ void __launch_bounds__(256)
split_kernel(const float* __restrict__ q, const float* __restrict__ v) {
    int i = (blockIdx.x * 256 + threadIdx.x) * 4;
    float4 fq = *(const float4*)(q + i);
    float4 fv = *(const float4*)(v + i);
    float xq[4] = {fq.x, fq.y, fq.z, fq.w};
    float xv[4] = {fv.x, fv.y, fv.z, fv.w};
    __nv_bfloat16 qh[4], ql[4], vh[4], vl[4];
#pragma unroll
    for (int j = 0; j < 4; ++j) {
        qh[j] = __float2bfloat16(xq[j]);
        ql[j] = __float2bfloat16(xq[j] - __bfloat162float(qh[j]));
        vh[j] = __float2bfloat16(xv[j]);
        vl[j] = __float2bfloat16(xv[j] - __bfloat162float(vh[j]));
    }
    *(ull*)(g_qhi + i) = *(ull*)qh;
    *(ull*)(g_qlo + i) = *(ull*)ql;
    *(ull*)(g_vhi + i) = *(ull*)vh;
    *(ull*)(g_vlo + i) = *(ull*)vl;
}

// =====================================================================
// wsplit kernel (after pass1): w[i,d] = inv_rs[i] * v[i,d] -> bf16 hi/lo
// overwrites g_vhi / g_vlo (v tiles no longer needed after pass1)
// =====================================================================
__global__ void __launch_bounds__(256)
wsplit_kernel(const float* __restrict__ v) {
    int e = (blockIdx.x * 256 + threadIdx.x) * 4;
    float s = g_inv_rs[e >> 7];         // row = e / DIM
    float4 f = *(const float4*)(v + e);
    float x[4] = {f.x * s, f.y * s, f.z * s, f.w * s};
    __nv_bfloat16 wh[4], wl[4];
#pragma unroll
    for (int j = 0; j < 4; ++j) {
        wh[j] = __float2bfloat16(x[j]);
        wl[j] = __float2bfloat16(x[j] - __bfloat162float(wh[j]));
    }
    *(ull*)(g_vhi + e) = *(ull*)wh;
    *(ull*)(g_vlo + e) = *(ull*)wl;
}

// =====================================================================
// Pass 1 (mma.sync bf16 split): u = exp(q.v^T / sqrt(D)) stored as bf16
// hi/lo into g_uhi/g_ulo; inv rowsums from f32 values.
// =====================================================================
#define PITCH 272
#define TILE_B (128 * PITCH)
#define OFF_QLO   0
#define OFF_VBUF(x) (TILE_B + (x) * (2 * TILE_B))
#define OFF_RS    (TILE_B + 4 * TILE_B)
#define P1_SMEM   (OFF_RS + 128 * 2 * 4)

__device__ __forceinline__ void stage_tile(uint32_t dst,
                                           const __nv_bfloat16* src, int t) {
#pragma unroll
    for (int it = 0; it < 8; ++it) {
        int id = it * 256 + t;
        int r = id >> 4, c = id & 15;
        cp_async16(dst + r * PITCH + c * 16, src + r * 128 + c * 8);
    }
}

__global__ void __launch_bounds__(256, 1)
pass1_kernel() {
    extern __shared__ char sm[];
    const uint32_t smb = smem_u32(sm);
    float* rsbuf = (float*)(sm + OFF_RS);

    const int b  = blockIdx.y;
    const int i0 = blockIdx.x * 128;
    const int t  = threadIdx.x;
    const int w  = t >> 5;
    const int l  = t & 31;
    const int wm = w & 3;
    const int wn = w >> 2;

    const __nv_bfloat16* qhg = g_qhi + ((size_t)b * SEQ + i0) * DIM;
    const __nv_bfloat16* qlg = g_qlo + ((size_t)b * SEQ + i0) * DIM;
    const __nv_bfloat16* vhg = g_vhi + (size_t)b * SEQ * DIM;
    const __nv_bfloat16* vlg = g_vlo + (size_t)b * SEQ * DIM;

    const int rA = (l & 7) + ((l >> 3) & 1) * 8;
    const int cA = (l >> 4) * 8;
    const int rB = (l & 7) + (l >> 4) * 8;
    const int cB = ((l >> 3) & 1) * 8;

    stage_tile(smb + OFF_VBUF(0), qhg, t);
    stage_tile(smb + OFF_QLO,     qlg, t);
    CP_COMMIT();
    CP_WAIT0();
    __syncthreads();

    unsigned qh[2][8][4];
#pragma unroll
    for (int f = 0; f < 2; ++f)
#pragma unroll
        for (int k8 = 0; k8 < 8; ++k8) {
            uint32_t addr = smb + OFF_VBUF(0) +
                (wm * 32 + f * 16 + rA) * PITCH + (k8 * 16 + cA) * 2;
            ldm4(qh[f][k8], addr);
        }
    __syncthreads();

    uint32_t qloA[2];
#pragma unroll
    for (int f = 0; f < 2; ++f)
        qloA[f] = smb + OFF_QLO + (wm * 32 + f * 16 + rA) * PITCH + cA * 2;

    uint32_t bRow[4];
#pragma unroll
    for (int p = 0; p < 4; ++p)
        bRow[p] = (wn * 64 + p * 16 + rB) * PITCH + cB * 2;

    stage_tile(smb + OFF_VBUF(0),          vhg, t);
    stage_tile(smb + OFF_VBUF(0) + TILE_B, vlg, t);
    CP_COMMIT();
    stage_tile(smb + OFF_VBUF(1),          vhg + 128 * DIM, t);
    stage_tile(smb + OFF_VBUF(1) + TILE_B, vlg + 128 * DIM, t);
    CP_COMMIT();

    // per-thread u output pointers (bf16 arrays)
    __nv_bfloat16 *uh[2], *ul[2];
#pragma unroll
    for (int f = 0; f < 2; ++f) {
        size_t base = ((size_t)(b * SEQ + i0 + wm * 32 + f * 16 + (l >> 2))) * SEQ
                      + wn * 64 + (l & 3) * 2;
        uh[f] = g_uhi + base;
        ul[f] = g_ulo + base;
    }

    float rs[2][2] = {{0.f, 0.f}, {0.f, 0.f}};
    const int NCHUNK = SEQ / 128;

    for (int c = 0; c < NCHUNK; ++c) {
        CP_WAIT1();
        __syncthreads();

        const uint32_t vh = smb + OFF_VBUF(c & 1);
        const uint32_t vl = vh + TILE_B;

        float acc[2][8][4];
#pragma unroll
        for (int f = 0; f < 2; ++f)
#pragma unroll
            for (int n = 0; n < 8; ++n)
#pragma unroll
                for (int x = 0; x < 4; ++x) acc[f][n][x] = 0.0f;

#pragma unroll
        for (int k8 = 0; k8 < 8; ++k8) {
            unsigned bh[4][4];
#pragma unroll
            for (int p = 0; p < 4; ++p)
                ldm4(bh[p], vh + bRow[p] + k8 * 32);
            unsigned al[2][4];
            ldm4(al[0], qloA[0] + k8 * 32);
            ldm4(al[1], qloA[1] + k8 * 32);
#pragma unroll
            for (int p = 0; p < 4; ++p)
#pragma unroll
                for (int h = 0; h < 2; ++h) {
                    const unsigned* bb = &bh[p][2 * h];
                    int n = 2 * p + h;
                    mma16816(acc[0][n], qh[0][k8], bb);
                    mma16816(acc[1][n], qh[1][k8], bb);
                    mma16816(acc[0][n], al[0], bb);
                    mma16816(acc[1][n], al[1], bb);
                }
            unsigned bl[4][4];
#pragma unroll
            for (int p = 0; p < 4; ++p)
                ldm4(bl[p], vl + bRow[p] + k8 * 32);
#pragma unroll
            for (int p = 0; p < 4; ++p)
#pragma unroll
                for (int h = 0; h < 2; ++h) {
                    const unsigned* bb = &bl[p][2 * h];
                    int n = 2 * p + h;
                    mma16816(acc[0][n], qh[0][k8], bb);
                    mma16816(acc[1][n], qh[1][k8], bb);
                }
        }

        __syncthreads();

        if (c + 2 < NCHUNK) {
            const uint32_t nb = smb + OFF_VBUF(c & 1);
            stage_tile(nb,          vhg + (size_t)(c + 2) * 128 * DIM, t);
            stage_tile(nb + TILE_B, vlg + (size_t)(c + 2) * 128 * DIM, t);
        }
        CP_COMMIT();

        // ---- epilogue: exp + rowsum + bf16 hi/lo store ----
#pragma unroll
        for (int f = 0; f < 2; ++f) {
#pragma unroll
            for (int n = 0; n < 8; ++n) {
                float e0 = exp2f(acc[f][n][0] * EXP2_SCALE);
                float e1 = exp2f(acc[f][n][1] * EXP2_SCALE);
                float e2 = exp2f(acc[f][n][2] * EXP2_SCALE);
                float e3 = exp2f(acc[f][n][3] * EXP2_SCALE);
                rs[f][0] += e0 + e1;
                rs[f][1] += e2 + e3;
                __nv_bfloat162 h01 = __floats2bfloat162_rn(e0, e1);
                __nv_bfloat162 h23 = __floats2bfloat162_rn(e2, e3);
                __nv_bfloat162 l01 = __floats2bfloat162_rn(
                    e0 - __bfloat162float(h01.x), e1 - __bfloat162float(h01.y));
                __nv_bfloat162 l23 = __floats2bfloat162_rn(
                    e2 - __bfloat162float(h23.x), e3 - __bfloat162float(h23.y));
                int o0 = c * 128 + n * 8;
                *(__nv_bfloat162*)(uh[f] + o0)           = h01;
                *(__nv_bfloat162*)(uh[f] + o0 + 8 * SEQ) = h23;
                *(__nv_bfloat162*)(ul[f] + o0)           = l01;
                *(__nv_bfloat162*)(ul[f] + o0 + 8 * SEQ) = l23;
            }
        }
    }

#pragma unroll
    for (int f = 0; f < 2; ++f)
#pragma unroll
        for (int h = 0; h < 2; ++h) {
            rs[f][h] += __shfl_xor_sync(0xffffffffu, rs[f][h], 1);
            rs[f][h] += __shfl_xor_sync(0xffffffffu, rs[f][h], 2);
        }
    if ((l & 3) == 0) {
#pragma unroll
        for (int f = 0; f < 2; ++f)
#pragma unroll
            for (int h = 0; h < 2; ++h) {
                int row = wm * 32 + f * 16 + h * 8 + (l >> 2);
                rsbuf[row * 2 + wn] = rs[f][h];
            }
    }
    __syncthreads();
    if (t < 128)
        g_inv_rs[b * SEQ + i0 + t] = 1.0f / (rsbuf[t * 2] + rsbuf[t * 2 + 1]);
}

// =====================================================================
// Pass 2 (mma.sync): out[j,d] = sum_i u[i,j] * w[i,d]  (w = inv_rs*v)
// attn[i,j] = (u_hi+u_lo)*inv_rs written during the same loop.
// CTA: 128 j x 128 d, 256 thr, i in 32 chunks of 64. No convert phase:
// all 4 MMA operand tiles staged directly via cp.async.
// =====================================================================
#define P2_I    64
#define APITCH  272
#define ATILE   (P2_I * APITCH)            // 17408
#define OFF_UH(x) ((x) * 4 * ATILE)
#define OFF_UL(x) ((x) * 4 * ATILE + ATILE)
#define OFF_WH(x) ((x) * 4 * ATILE + 2 * ATILE)
#define OFF_WL(x) ((x) * 4 * ATILE + 3 * ATILE)
#define P2_SMEM   (8 * ATILE)              // 139264

__device__ __forceinline__ void stage_b16(uint32_t dst, const __nv_bfloat16* src,
                                          int stride, int t) {
#pragma unroll
    for (int it = 0; it < 4; ++it) {
        int id = it * 256 + t;
        int r = id >> 4, c = id & 15;
        cp_async16(dst + r * APITCH + c * 16, src + (size_t)r * stride + c * 8);
    }
}

__global__ void __launch_bounds__(256, 1)
pass2_kernel(float* __restrict__ attn, float* __restrict__ out) {
    extern __shared__ char sm[];
    const uint32_t smb = smem_u32(sm);

    const int b  = blockIdx.y;
    const int j0 = blockIdx.x * 128;
    const int t  = threadIdx.x;
    const int w  = t >> 5;
    const int l  = t & 31;
    const int wm = w & 3;
    const int wn = w >> 2;

    float* ab = attn + (size_t)b * SEQ * SEQ;
    const __nv_bfloat16* uhg = g_uhi + (size_t)b * SEQ * SEQ + j0;
    const __nv_bfloat16* ulg = g_ulo + (size_t)b * SEQ * SEQ + j0;
    const __nv_bfloat16* whg = g_vhi + (size_t)b * SEQ * DIM;
    const __nv_bfloat16* wlg = g_vlo + (size_t)b * SEQ * DIM;
    const float* irs = g_inv_rs + b * SEQ;
    float*       ob  = out + (size_t)b * SEQ * DIM;

    const int rAT = (l & 7) + ((l >> 4) & 1) * 8;
    const int cAT = ((l >> 3) & 1) * 8;
    const int rBT = (l & 7) + ((l >> 3) & 1) * 8;
    const int cBT = (l >> 4) * 8;

    // attn-write lane mapping: 16 lanes cover one 256B row (conflict-free LDS.128)
    const int aw_sub = l >> 4;    // 0..1
    const int aw_c16 = l & 15;    // 16B column group

    stage_b16(smb + OFF_UH(0), uhg, SEQ, t);
    stage_b16(smb + OFF_UL(0), ulg, SEQ, t);
    stage_b16(smb + OFF_WH(0), whg, DIM, t);
    stage_b16(smb + OFF_WL(0), wlg, DIM, t);
    CP_COMMIT();

    float acc[2][8][4];
#pragma unroll
    for (int f = 0; f < 2; ++f)
#pragma unroll
        for (int n = 0; n < 8; ++n)
#pragma unroll
            for (int x = 0; x < 4; ++x) acc[f][n][x] = 0.0f;

    const int NCHUNK = SEQ / P2_I;   // 32

    for (int c = 0; c < NCHUNK; ++c) {
        const int bu = c & 1;
        const int i0c = c * P2_I;

        CP_WAIT0();
        __syncthreads();

        if (c + 1 < NCHUNK) {
            const int nb = (c + 1) & 1;
            stage_b16(smb + OFF_UH(nb), uhg + (size_t)(i0c + P2_I) * SEQ, SEQ, t);
            stage_b16(smb + OFF_UL(nb), ulg + (size_t)(i0c + P2_I) * SEQ, SEQ, t);
            stage_b16(smb + OFF_WH(nb), whg + (size_t)(i0c + P2_I) * DIM, DIM, t);
            stage_b16(smb + OFF_WL(nb), wlg + (size_t)(i0c + P2_I) * DIM, DIM, t);
        }
        CP_COMMIT();

        // ---- attn write: (u_hi + u_lo) * inv_rs -> gmem (read-only smem) ----
#pragma unroll
        for (int it = 0; it < 4; ++it) {
            int row = w * 2 + aw_sub + it * 16;
            float s = __ldg(irs + i0c + row);
            uint32_t ha = smb + OFF_UH(bu) + row * APITCH + aw_c16 * 16;
            uint32_t la = smb + OFF_UL(bu) + row * APITCH + aw_c16 * 16;
            unsigned hr[4], lr[4];
            asm volatile("ld.shared.v4.b32 {%0,%1,%2,%3}, [%4];"
                         : "=r"(hr[0]), "=r"(hr[1]), "=r"(hr[2]), "=r"(hr[3]) : "r"(ha));
            asm volatile("ld.shared.v4.b32 {%0,%1,%2,%3}, [%4];"
                         : "=r"(lr[0]), "=r"(lr[1]), "=r"(lr[2]), "=r"(lr[3]) : "r"(la));
            float o[8];
#pragma unroll
            for (int x = 0; x < 4; ++x) {
                __nv_bfloat162 h2 = *(__nv_bfloat162*)&hr[x];
                __nv_bfloat162 l2 = *(__nv_bfloat162*)&lr[x];
                o[2 * x + 0] = (__bfloat162float(h2.x) + __bfloat162float(l2.x)) * s;
                o[2 * x + 1] = (__bfloat162float(h2.y) + __bfloat162float(l2.y)) * s;
            }
            float* grow = ab + (size_t)(i0c + row) * SEQ + j0 + aw_c16 * 8;
            *(float4*)(grow)     = make_float4(o[0], o[1], o[2], o[3]);
            *(float4*)(grow + 4) = make_float4(o[4], o[5], o[6], o[7]);
        }

        // ---- MMA ----
        const uint32_t UH = smb + OFF_UH(bu);
        const uint32_t UL = smb + OFF_UL(bu);
        const uint32_t WH = smb + OFF_WH(bu);
        const uint32_t WL = smb + OFF_WL(bu);
#pragma unroll
        for (int k8 = 0; k8 < P2_I / 16; ++k8) {
            const uint32_t kro = (k8 * 16) * APITCH;
            unsigned ahf[2][4], alf[2][4];
#pragma unroll
            for (int f = 0; f < 2; ++f) {
                uint32_t coff = rAT * APITCH + (wm * 32 + f * 16 + cAT) * 2;
                ldm4t(ahf[f], UH + kro + coff);
                ldm4t(alf[f], UL + kro + coff);
            }
            unsigned bh[4][4];
#pragma unroll
            for (int p = 0; p < 4; ++p) {
                uint32_t coff = rBT * APITCH + (wn * 64 + p * 16 + cBT) * 2;
                ldm4t(bh[p], WH + kro + coff);
            }
#pragma unroll
            for (int p = 0; p < 4; ++p)
#pragma unroll
                for (int h = 0; h < 2; ++h) {
                    const unsigned* bb = &bh[p][2 * h];
                    int n = 2 * p + h;
                    mma16816(acc[0][n], ahf[0], bb);
                    mma16816(acc[1][n], ahf[1], bb);
                    mma16816(acc[0][n], alf[0], bb);
                    mma16816(acc[1][n], alf[1], bb);
                }
            unsigned bl[4][4];
#pragma unroll
            for (int p = 0; p < 4; ++p) {
                uint32_t coff = rBT * APITCH + (wn * 64 + p * 16 + cBT) * 2;
                ldm4t(bl[p], WL + kro + coff);
            }
#pragma unroll
            for (int p = 0; p < 4; ++p)
#pragma unroll
                for (int h = 0; h < 2; ++h) {
                    const unsigned* bb = &bl[p][2 * h];
                    int n = 2 * p + h;
                    mma16816(acc[0][n], ahf[0], bb);
                    mma16816(acc[1][n], ahf[1], bb);
                }
        }
    }

    // ---- store out[j,d] ----
#pragma unroll
    for (int f = 0; f < 2; ++f) {
        int jr = j0 + wm * 32 + f * 16 + (l >> 2);
        float* r0 = ob + (size_t)jr * DIM + wn * 64 + (l & 3) * 2;
#pragma unroll
        for (int n = 0; n < 8; ++n) {
            *(float2*)(r0 + n * 8)           = make_float2(acc[f][n][0], acc[f][n][1]);
            *(float2*)(r0 + n * 8 + 8 * DIM) = make_float2(acc[f][n][2], acc[f][n][3]);
        }
    }
}

// =====================================================================
extern "C" void kernel_launch(void* const* d_in, const int* in_sizes, int n_in,
                              void* d_out, int out_size) {
    const float* q = (const float*)d_in[0];
    // d_in[1] (k) unused by the reference
    const float* v = (const float*)d_in[2];

    float* out  = (float*)d_out;                      // [8,2048,128]
    float* attn = out + (size_t)BATCH * SEQ * DIM;    // [8,2048,2048]

    cudaFuncSetAttribute(pass1_kernel,
                         cudaFuncAttributeMaxDynamicSharedMemorySize, P1_SMEM);
    cudaFuncSetAttribute(pass2_kernel,
                         cudaFuncAttributeMaxDynamicSharedMemorySize, P2_SMEM);

    split_kernel<<<(BATCH * SEQ * DIM) / (256 * 4), 256>>>(q, v);

    dim3 g1(SEQ / 128, BATCH);
    pass1_kernel<<<g1, 256, P1_SMEM>>>();

    wsplit_kernel<<<(BATCH * SEQ * DIM) / (256 * 4), 256>>>(v);

    dim3 g2(SEQ / 128, BATCH);
    pass2_kernel<<<g2, 256, P2_SMEM>>>(attn, out);
}